// round 2
// baseline (speedup 1.0000x reference)
#include <cuda_runtime.h>
#include <cuda_bf16.h>

// Problem constants
#define TT    8192
#define NN    10
#define FIN   7
#define NF    70      // N*F_IN
#define NFP   72      // padded
#define OO    64
#define HH    512
#define G4    2048    // 4*H
#define LAT   128
#define EE    40
#define RR    2
#define NBLK  64      // recurrent blocks
#define HC    8       // H cells per block (512/64)

// Scratch (device globals; no dynamic allocation allowed)
__device__ float         g_G[NN * NN * FIN * OO];   // [n][m][f][o]  (44800)
__device__ float         g_M[G4 * NFP];             // [2048][72] padded
__device__ float         g_biasx[G4];
__device__ float4        g_h4[HH / 4];              // current h (512 floats)
__device__ float4        g_hs4[TT * HH / 4];        // all h_t   (16.8 MB)
__device__ unsigned int  g_arr;                     // barrier counter

// ---------------------------------------------------------------------------
// K1: build G[n][m][f][o] from edges:  G = sum_r invcnt[r][n]*c[r][n][m]*W_rel[r]
//     + (n==m) * W_root
// ---------------------------------------------------------------------------
__global__ void k1_build_G(const float* __restrict__ Wrel,
                           const float* __restrict__ Wroot,
                           const int*   __restrict__ eidx,
                           const int*   __restrict__ etyp) {
    __shared__ int   cc[RR][NN][NN];
    __shared__ float inv[RR][NN];
    int tid = threadIdx.x;
    for (int i = tid; i < RR * NN * NN; i += 256) ((int*)cc)[i] = 0;
    __syncthreads();
    if (tid < EE) {
        int s = eidx[tid];
        int d = eidx[EE + tid];
        int r = etyp[tid];
        atomicAdd(&cc[r][d][s], 1);
    }
    __syncthreads();
    if (tid < RR * NN) {
        int r = tid / NN, n = tid % NN;
        int cnt = 0;
        for (int m = 0; m < NN; m++) cnt += cc[r][n][m];
        inv[r][n] = 1.0f / fmaxf((float)cnt, 1.0f);
    }
    __syncthreads();
    for (int idx = tid; idx < NN * NN * FIN * OO; idx += 256) {
        int o = idx & 63;
        int f = (idx >> 6) % FIN;
        int m = (idx / (FIN * OO)) % NN;
        int n = idx / (NN * FIN * OO);
        float v = inv[0][n] * (float)cc[0][n][m] * Wrel[(0 * FIN + f) * OO + o]
                + inv[1][n] * (float)cc[1][n][m] * Wrel[(1 * FIN + f) * OO + o];
        if (n == m) v += Wroot[f * OO + o];
        g_G[idx] = v;
    }
}

// ---------------------------------------------------------------------------
// K2: M[g][j] = sum_{n,o} W_ih[g][n*64+o] * G[n][j/7][j%7][o]   (j = m*7+f)
//     biasx[g] = b_ih[g] + b_hh[g] + sum_{n,o} W_ih[g][n*64+o]*b_rgcn[o]
//     32 blocks x 256 threads; each block does 64 g-rows x 72(->80) cols.
//     Thread tile: 4 rows x 5 cols (16x16 threads -> 64x80, writes guarded).
// ---------------------------------------------------------------------------
__global__ void k2_build_M(const float* __restrict__ Wih,
                           const float* __restrict__ bih,
                           const float* __restrict__ bhh,
                           const float* __restrict__ brg) {
    __shared__ float Aw[64][65];
    __shared__ float Bg[80][65];
    int g0  = blockIdx.x * 64;
    int tid = threadIdx.x;
    int ty  = tid >> 4, tx = tid & 15;
    float acc[4][5];
#pragma unroll
    for (int u = 0; u < 4; u++)
#pragma unroll
        for (int v = 0; v < 5; v++) acc[u][v] = 0.0f;

    for (int n = 0; n < NN; n++) {
        __syncthreads();
        for (int i = tid; i < 64 * 64; i += 256) {
            int r = i >> 6, c = i & 63;
            Aw[r][c] = Wih[(g0 + r) * (NN * OO) + n * OO + c];
        }
        for (int i = tid; i < 80 * 64; i += 256) {
            int j = i >> 6, o = i & 63;
            Bg[j][o] = (j < NF)
                ? g_G[((n * NN + (j / FIN)) * FIN + (j % FIN)) * OO + o]
                : 0.0f;
        }
        __syncthreads();
        for (int o = 0; o < 64; o++) {
            float a[4], b[5];
#pragma unroll
            for (int u = 0; u < 4; u++) a[u] = Aw[ty * 4 + u][o];
#pragma unroll
            for (int v = 0; v < 5; v++) b[v] = Bg[tx * 5 + v][o];
#pragma unroll
            for (int u = 0; u < 4; u++)
#pragma unroll
                for (int v = 0; v < 5; v++) acc[u][v] += a[u] * b[v];
        }
    }
#pragma unroll
    for (int u = 0; u < 4; u++)
#pragma unroll
        for (int v = 0; v < 5; v++) {
            int j = tx * 5 + v;
            if (j < NFP)
                g_M[(g0 + ty * 4 + u) * NFP + j] = acc[u][v];
        }

    __syncthreads();
    if (tid < 64) {
        int g = g0 + tid;
        float s = bih[g] + bhh[g];
        for (int q = 0; q < NN * OO; q++) s += Wih[g * (NN * OO) + q] * brg[q & 63];
        g_biasx[g] = s;
    }
}

// ---------------------------------------------------------------------------
// K3: reset barrier + h (must run before K4 on every graph replay)
// ---------------------------------------------------------------------------
__global__ void k3_reset() {
    int tid = threadIdx.x;
    if (tid == 0) g_arr = 0u;
    if (tid < HH / 4) {
        float4 z = {0.f, 0.f, 0.f, 0.f};
        g_h4[tid] = z;
    }
}

// ---------------------------------------------------------------------------
// K4: sequential LSTM. 64 blocks x 128 threads. Block b owns h cells
//     [b*8, b*8+8). Thread (w=tid/32, lane=tid%32): gate=lane/8, cell=lane%8,
//     owns W_hh row (gate*512 + b*8 + cell), column chunk [w*128, w*128+128)
//     entirely in registers. Global spin barrier per step.
// ---------------------------------------------------------------------------
__global__ void __launch_bounds__(128, 1)
k4_lstm(const float* __restrict__ x, const float* __restrict__ Whh) {
    __shared__ float sh_h[HH];
    __shared__ float sh_x[NFP];
    __shared__ float sh_part[4][32];

    const int tid  = threadIdx.x;
    const int w    = tid >> 5;
    const int lane = tid & 31;
    const int bid  = blockIdx.x;
    const int gate = lane >> 3;
    const int cell = lane & 7;
    const int grow = gate * HH + bid * HC + cell;

    // W_hh slice in registers: 128 floats as 32 float4
    float4 whh4[32];
    const float4* wp = (const float4*)(Whh + (size_t)grow * HH + w * 128);
#pragma unroll
    for (int i = 0; i < 32; i++) whh4[i] = wp[i];

    // M slice: 18 cols (padded) per thread
    float mr[18];
#pragma unroll
    for (int i = 0; i < 18; i++) mr[i] = g_M[grow * NFP + w * 18 + i];

    const float bx = (w == 0) ? g_biasx[grow] : 0.0f;

    // init shared h = 0, x pad = 0
    {
        float4 z = {0.f, 0.f, 0.f, 0.f};
        ((float4*)sh_h)[tid] = z;
        if (tid < NFP) sh_x[tid] = 0.0f;
    }
    float xreg = (tid < NF) ? __ldcg(x + tid) : 0.0f;
    float c = 0.0f;
    unsigned int target = 0;

    float* gh  = (float*)g_h4;
    float* ghs = (float*)g_hs4;

    for (int t = 0; t < TT; t++) {
        if (tid < NFP) sh_x[tid] = xreg;
        // prefetch next x (latency hidden over whole step)
        xreg = (tid < NF && t + 1 < TT) ? __ldcg(x + (size_t)(t + 1) * NF + tid)
                                        : 0.0f;
        __syncthreads();

        float a0 = (w == 0) ? bx : 0.0f, a1 = 0.f, a2 = 0.f, a3 = 0.f;

        // input part: M-slice . x[t]
        const float* xs = sh_x + w * 18;
#pragma unroll
        for (int i = 0; i < 18; i += 2) {
            a0 += mr[i] * xs[i];
            a1 += mr[i + 1] * xs[i + 1];
        }
        // recurrent part: W_hh-slice . h  (h chunk broadcast within warp)
        const float4* hs4 = ((const float4*)sh_h) + w * 32;
#pragma unroll
        for (int i = 0; i < 32; i++) {
            float4 hv = hs4[i];
            a0 += whh4[i].x * hv.x;
            a1 += whh4[i].y * hv.y;
            a2 += whh4[i].z * hv.z;
            a3 += whh4[i].w * hv.w;
        }
        sh_part[w][lane] = (a0 + a1) + (a2 + a3);
        __syncthreads();

        if (w == 0) {
            float val = sh_part[0][lane] + sh_part[1][lane] +
                        sh_part[2][lane] + sh_part[3][lane];
            float act = (gate == 2) ? tanhf(val)
                                    : (1.0f / (1.0f + expf(-val)));
            float fv = __shfl_sync(0xffffffffu, act, 8 + cell);
            float gv = __shfl_sync(0xffffffffu, act, 16 + cell);
            float ov = __shfl_sync(0xffffffffu, act, 24 + cell);
            if (lane < HC) {
                c = fv * c + act * gv;          // act == sigmoid(i) on lanes 0..7
                float hv = ov * tanhf(c);
                __stcg(&gh[bid * HC + lane], hv);
                ghs[(size_t)t * HH + bid * HC + lane] = hv;
            }
            __threadfence();
            __syncwarp();
            if (lane == 0) atomicAdd(&g_arr, 1u);
        }

        target += NBLK;
        if (tid == 0) {
            volatile unsigned int* p = &g_arr;
            while (*p < target) { }
            __threadfence();   // acquire: order h reads after counter observation
        }
        __syncthreads();

        // broadcast full h from L2 into shared
        float4 hv4 = __ldcg(g_h4 + tid);
        ((float4*)sh_h)[tid] = hv4;
    }
}

// ---------------------------------------------------------------------------
// K5: post-processing per 8 timesteps: hfc = relu(fc1 h + b), split mu/logvar,
//     z = mu + eps*exp(0.5 lv), rec = sigmoid(fc2 z + b). 1024 blocks x 256.
// ---------------------------------------------------------------------------
#define REC_OFF 0
#define MU_OFF  (TT * NN * FIN)                 // 573440
#define LV_OFF  (MU_OFF + TT * LAT)             // 1622016

__global__ void __launch_bounds__(256)
k5_post(const float* __restrict__ eps,
        const float* __restrict__ fc1w, const float* __restrict__ fc1b,
        const float* __restrict__ fc2w, const float* __restrict__ fc2b,
        float* __restrict__ out) {
    __shared__ float shh[8 * HH];
    __shared__ float shfc[8][256];
    __shared__ float shz[8][LAT];

    int tid  = threadIdx.x;
    int w    = tid >> 5;
    int lane = tid & 31;
    int t0   = blockIdx.x * 8;

    for (int i = tid; i < 8 * HH / 4; i += 256)
        ((float4*)shh)[i] = ((const float4*)g_hs4)[(size_t)t0 * (HH / 4) + i];
    __syncthreads();

    // fc1: 256 outputs, warp w does rows [w*32, w*32+32)
    for (int i = 0; i < 32; i++) {
        int j = w * 32 + i;
        float wr[16];
#pragma unroll
        for (int u = 0; u < 16; u++)
            wr[u] = __ldg(fc1w + (size_t)j * HH + u * 32 + lane);
#pragma unroll
        for (int ttk = 0; ttk < 8; ttk++) {
            float p = 0.0f;
#pragma unroll
            for (int u = 0; u < 16; u++)
                p += wr[u] * shh[ttk * HH + u * 32 + lane];
            p += __shfl_xor_sync(0xffffffffu, p, 16);
            p += __shfl_xor_sync(0xffffffffu, p, 8);
            p += __shfl_xor_sync(0xffffffffu, p, 4);
            p += __shfl_xor_sync(0xffffffffu, p, 2);
            p += __shfl_xor_sync(0xffffffffu, p, 1);
            if (lane == 0) shfc[ttk][j] = fmaxf(p + fc1b[j], 0.0f);
        }
    }
    __syncthreads();

    // VAE reparam + mu / log_var outputs
    for (int i = tid; i < 8 * LAT; i += 256) {
        int ttk = i >> 7, j = i & 127;
        int t = t0 + ttk;
        float mu = shfc[ttk][j];
        float lv = shfc[ttk][LAT + j];
        out[MU_OFF + (size_t)t * LAT + j] = mu;
        out[LV_OFF + (size_t)t * LAT + j] = lv;
        shz[ttk][j] = mu + eps[(size_t)t * LAT + j] * expf(0.5f * lv);
    }
    __syncthreads();

    // fc2 + sigmoid -> rec
    for (int i = 0; i < 9; i++) {
        int j = w + 8 * i;
        if (j < NF) {
            float wr[4];
#pragma unroll
            for (int u = 0; u < 4; u++)
                wr[u] = __ldg(fc2w + (size_t)j * LAT + u * 32 + lane);
#pragma unroll
            for (int ttk = 0; ttk < 8; ttk++) {
                float p = 0.0f;
#pragma unroll
                for (int u = 0; u < 4; u++)
                    p += wr[u] * shz[ttk][u * 32 + lane];
                p += __shfl_xor_sync(0xffffffffu, p, 16);
                p += __shfl_xor_sync(0xffffffffu, p, 8);
                p += __shfl_xor_sync(0xffffffffu, p, 4);
                p += __shfl_xor_sync(0xffffffffu, p, 2);
                p += __shfl_xor_sync(0xffffffffu, p, 1);
                if (lane == 0)
                    out[REC_OFF + (size_t)(t0 + ttk) * NF + j] =
                        1.0f / (1.0f + expf(-(p + fc2b[j])));
            }
        }
    }
}

// ---------------------------------------------------------------------------
extern "C" void kernel_launch(void* const* d_in, const int* in_sizes, int n_in,
                              void* d_out, int out_size) {
    const float* x     = (const float*)d_in[0];
    const float* eps   = (const float*)d_in[1];
    const float* Wrel  = (const float*)d_in[2];
    const float* Wroot = (const float*)d_in[3];
    const float* brg   = (const float*)d_in[4];
    const float* Wih   = (const float*)d_in[5];
    const float* Whh   = (const float*)d_in[6];
    const float* bih   = (const float*)d_in[7];
    const float* bhh   = (const float*)d_in[8];
    const float* fc1w  = (const float*)d_in[9];
    const float* fc1b  = (const float*)d_in[10];
    const float* fc2w  = (const float*)d_in[11];
    const float* fc2b  = (const float*)d_in[12];
    const int*   eidx  = (const int*)d_in[13];
    const int*   etyp  = (const int*)d_in[14];
    float* out = (float*)d_out;

    k1_build_G<<<1, 256>>>(Wrel, Wroot, eidx, etyp);
    k2_build_M<<<32, 256>>>(Wih, bih, bhh, brg);
    k3_reset<<<1, 256>>>();
    k4_lstm<<<NBLK, 128>>>(x, Whh);
    k5_post<<<TT / 8, 256>>>(eps, fc1w, fc1b, fc2w, fc2b, out);
}